// round 2
// baseline (speedup 1.0000x reference)
#include <cuda_runtime.h>

#define BATCH   524288
#define MTILE   64
#define NBLOCKS (BATCH / MTILE)   // 8192

// Scratch (static __device__ globals — no allocation)
__device__ float  g_rewards[BATCH];
__device__ double g_acc[2];   // [0]=sum, [1]=sumsq (fp64)
__device__ float  g_np[2];    // [0]=new_mean, [1]=1/(std+1e-8)

__global__ void k_init() { g_acc[0] = 0.0; g_acc[1] = 0.0; }

// ---------------------------------------------------------------------------
// GEMM core: acc[4][8] = A[64,K] @ W[128,K]^T tile for this thread.
// A: row-major in SMEM (pitch = K). W: global, row-major [128,K].
// W panels of 16 k-columns staged into SMEM (pitch 132 to dodge conflicts).
// Thread (tx,ty): rows r0=4*ty..+3, cols c0=8*tx..+7. 256 threads.
// ---------------------------------------------------------------------------
template <int K>
__device__ __forceinline__ void gemm_acc(
    const float* __restrict__ A,
    const float* __restrict__ W,
    float* __restrict__ Wc,
    float acc[4][8], int tid, int tx, int ty)
{
#pragma unroll
    for (int i = 0; i < 4; i++)
#pragma unroll
        for (int j = 0; j < 8; j++) acc[i][j] = 0.f;

    const int r0 = ty * 4;
    const int c4 = tx * 2;   // float4 column index into Wc row

    for (int kk = 0; kk < K; kk += 16) {
        // stage W[0:128][kk:kk+16] -> Wc[k_local][c], k_local-major rows of 132
#pragma unroll
        for (int e = 0; e < 2; e++) {
            int idx = tid + e * 256;       // 0..511
            int c   = idx >> 2;            // 0..127
            int kg  = idx & 3;             // 0..3 (group of 4 k)
            float4 g = *(const float4*)(W + c * K + kk + kg * 4);
            float* w = Wc + (kg * 4) * 132 + c;
            w[0]       = g.x;
            w[132]     = g.y;
            w[264]     = g.z;
            w[396]     = g.w;
        }
        __syncthreads();

#pragma unroll
        for (int k = 0; k < 16; k++) {
            float a0 = A[(r0 + 0) * K + kk + k];
            float a1 = A[(r0 + 1) * K + kk + k];
            float a2 = A[(r0 + 2) * K + kk + k];
            float a3 = A[(r0 + 3) * K + kk + k];
            const float4* wr = (const float4*)(Wc + k * 132);
            float4 w0 = wr[c4];
            float4 w1 = wr[c4 + 1];
            float w[8] = {w0.x, w0.y, w0.z, w0.w, w1.x, w1.y, w1.z, w1.w};
#pragma unroll
            for (int j = 0; j < 8; j++) {
                acc[0][j] = fmaf(a0, w[j], acc[0][j]);
                acc[1][j] = fmaf(a1, w[j], acc[1][j]);
                acc[2][j] = fmaf(a2, w[j], acc[2][j]);
                acc[3][j] = fmaf(a3, w[j], acc[3][j]);
            }
        }
        __syncthreads();
    }
}

// relu(acc + b) -> H (row-major, pitch 128)
__device__ __forceinline__ void epilogue_relu(
    const float acc[4][8], const float* __restrict__ b,
    float* __restrict__ H, int r0, int c0)
{
    float bv[8];
#pragma unroll
    for (int j = 0; j < 8; j++) bv[j] = __ldg(&b[c0 + j]);
#pragma unroll
    for (int i = 0; i < 4; i++)
#pragma unroll
        for (int j = 0; j < 8; j++)
            H[(r0 + i) * 128 + c0 + j] = fmaxf(acc[i][j] + bv[j], 0.f);
}

// ---------------------------------------------------------------------------
// Fused MLP kernel: one block = 64 samples. Computes both nets, per-sample
// MSE reward, writes g_rewards, and fp64-accumulates sum/sumsq.
// ---------------------------------------------------------------------------
__global__ void __launch_bounds__(256, 2) k_mlp(
    const float* __restrict__ obs,
    const float* __restrict__ tW1, const float* __restrict__ tb1,
    const float* __restrict__ tW2, const float* __restrict__ tb2,
    const float* __restrict__ tW3, const float* __restrict__ tb3,
    const float* __restrict__ pW1, const float* __restrict__ pb1,
    const float* __restrict__ pW2, const float* __restrict__ pb2,
    const float* __restrict__ pW3, const float* __restrict__ pb3)
{
    extern __shared__ float sm[];
    float* X    = sm;              // 64*64   = 4096 floats
    float* H0   = sm + 4096;       // 64*128  = 8192
    float* H1   = sm + 12288;      // 64*128  = 8192
    float* Wc   = sm + 20480;      // 16*132  = 2112
    float* part = sm + 22592;      // 64*17   = 1088
    // total 23680 floats = 94720 bytes

    const int tid = threadIdx.x;
    const int tx = tid & 15, ty = tid >> 4;
    const int r0 = ty * 4, c0 = tx * 8;

    // Load obs tile (contiguous 64*64 floats per block)
    {
        const float4* src = (const float4*)(obs + (size_t)blockIdx.x * (MTILE * 64));
        float4* dst = (float4*)X;
#pragma unroll
        for (int e = 0; e < 4; e++) dst[tid + e * 256] = src[tid + e * 256];
    }
    __syncthreads();

    float acc[4][8];
    float ot[4][8];   // target-net final-layer output, kept in registers

    // ---- target net ----
    gemm_acc<64>(X, tW1, Wc, acc, tid, tx, ty);
    epilogue_relu(acc, tb1, H0, r0, c0);
    __syncthreads();

    gemm_acc<128>(H0, tW2, Wc, acc, tid, tx, ty);
    epilogue_relu(acc, tb2, H1, r0, c0);
    __syncthreads();

    gemm_acc<128>(H1, tW3, Wc, acc, tid, tx, ty);
    {
        float bv[8];
#pragma unroll
        for (int j = 0; j < 8; j++) bv[j] = __ldg(&tb3[c0 + j]);
#pragma unroll
        for (int i = 0; i < 4; i++)
#pragma unroll
            for (int j = 0; j < 8; j++) ot[i][j] = acc[i][j] + bv[j];
    }
    // no smem written; trailing sync inside gemm_acc protects Wc reuse

    // ---- predictor net ----
    gemm_acc<64>(X, pW1, Wc, acc, tid, tx, ty);
    epilogue_relu(acc, pb1, H0, r0, c0);
    __syncthreads();

    gemm_acc<128>(H0, pW2, Wc, acc, tid, tx, ty);
    epilogue_relu(acc, pb2, H1, r0, c0);
    __syncthreads();

    gemm_acc<128>(H1, pW3, Wc, acc, tid, tx, ty);

    // diff^2 partial row sums
    float rs[4] = {0.f, 0.f, 0.f, 0.f};
    {
        float bv[8];
#pragma unroll
        for (int j = 0; j < 8; j++) bv[j] = __ldg(&pb3[c0 + j]);
#pragma unroll
        for (int i = 0; i < 4; i++) {
#pragma unroll
            for (int j = 0; j < 8; j++) {
                float d = (acc[i][j] + bv[j]) - ot[i][j];
                rs[i] = fmaf(d, d, rs[i]);
            }
        }
    }
#pragma unroll
    for (int i = 0; i < 4; i++) part[(r0 + i) * 17 + tx] = rs[i];
    __syncthreads();

    // one thread per row: finish reward, then warp-reduce fp64 sum/sumsq
    if (tid < 64) {
        const float* p = part + tid * 17;
        float s = 0.f;
#pragma unroll
        for (int t = 0; t < 16; t++) s += p[t];
        float rw = s * (1.0f / 128.0f);
        g_rewards[blockIdx.x * MTILE + tid] = rw;

        double ds = (double)rw;
        double dq = ds * ds;
#pragma unroll
        for (int off = 16; off > 0; off >>= 1) {
            ds += __shfl_down_sync(0xffffffffu, ds, off);
            dq += __shfl_down_sync(0xffffffffu, dq, off);
        }
        if ((tid & 31) == 0) {
            atomicAdd(&g_acc[0], ds);
            atomicAdd(&g_acc[1], dq);
        }
    }
}

// ---------------------------------------------------------------------------
// Chan-merge Welford stats (exact reference math, fp64)
// ---------------------------------------------------------------------------
__global__ void k_stats(const float* __restrict__ rmean,
                        const float* __restrict__ rm2,
                        const float* __restrict__ rcount)
{
    double n     = (double)BATCH;
    double sum   = g_acc[0];
    double sq    = g_acc[1];
    double bmean = sum / n;
    double bm2   = sq - sum * sum / n;       // sum((r-bmean)^2)
    double rc    = (double)rcount[0];
    double newc  = rc + n;
    double delta = bmean - (double)rmean[0];
    double nmean = (double)rmean[0] + delta * n / newc;
    double nm2   = (double)rm2[0] + bm2 + delta * delta * rc * n / newc;
    double sd    = (newc > 1.0) ? sqrt(nm2 / (newc - 1.0)) : 1.0;
    g_np[0] = (float)nmean;
    g_np[1] = (float)(1.0 / (sd + 1e-8));
}

__global__ void k_norm(float* __restrict__ out)
{
    int i = blockIdx.x * blockDim.x + threadIdx.x;   // float4 index
    float m = g_np[0], v = g_np[1];
    float4 r = ((const float4*)g_rewards)[i];
    float4 o;
    o.x = (r.x - m) * v;
    o.y = (r.y - m) * v;
    o.z = (r.z - m) * v;
    o.w = (r.w - m) * v;
    ((float4*)out)[i] = o;
}

// ---------------------------------------------------------------------------
extern "C" void kernel_launch(void* const* d_in, const int* in_sizes, int n_in,
                              void* d_out, int out_size)
{
    const float* obs    = (const float*)d_in[0];
    const float* rmean  = (const float*)d_in[1];
    const float* rm2    = (const float*)d_in[2];
    const float* rcount = (const float*)d_in[3];
    const float* tW1 = (const float*)d_in[4];  const float* tb1 = (const float*)d_in[5];
    const float* tW2 = (const float*)d_in[6];  const float* tb2 = (const float*)d_in[7];
    const float* tW3 = (const float*)d_in[8];  const float* tb3 = (const float*)d_in[9];
    const float* pW1 = (const float*)d_in[10]; const float* pb1 = (const float*)d_in[11];
    const float* pW2 = (const float*)d_in[12]; const float* pb2 = (const float*)d_in[13];
    const float* pW3 = (const float*)d_in[14]; const float* pb3 = (const float*)d_in[15];

    const int smem_bytes = 23680 * (int)sizeof(float);   // 94720
    cudaFuncSetAttribute(k_mlp, cudaFuncAttributeMaxDynamicSharedMemorySize, smem_bytes);

    k_init<<<1, 1>>>();
    k_mlp<<<NBLOCKS, 256, smem_bytes>>>(obs,
                                        tW1, tb1, tW2, tb2, tW3, tb3,
                                        pW1, pb1, pW2, pb2, pW3, pb3);
    k_stats<<<1, 1>>>(rmean, rm2, rcount);
    k_norm<<<BATCH / 4 / 256, 256>>>((float*)d_out);
}